// round 1
// baseline (speedup 1.0000x reference)
#include <cuda_runtime.h>

#define N_TOK 4096
#define D_MODEL 1024
#define NH 16
#define HD 64

// Scratch (head-major [H][N][HD]) — __device__ globals, no allocation.
__device__ float g_Q[NH * N_TOK * HD];
__device__ float g_K[NH * N_TOK * HD];
__device__ float g_V[NH * N_TOK * HD];
__device__ float g_C[NH * N_TOK * HD];

// ---------------------------------------------------------------------------
// QKV projection: C[m,e] = sum_k x[m,k] * W[k,e], written head-major.
// 128x128x16 tiles, 8x8 per thread, 256 threads. grid.z selects Wq/Wk/Wv.
// ---------------------------------------------------------------------------
__global__ __launch_bounds__(256) void qkv_gemm(const float* __restrict__ x,
                                                const float* __restrict__ Wq,
                                                const float* __restrict__ Wk,
                                                const float* __restrict__ Wv) {
    __shared__ float As[16][128];
    __shared__ float Bs[16][128];

    const float* W;
    float* out;
    if (blockIdx.z == 0)      { W = Wq; out = g_Q; }
    else if (blockIdx.z == 1) { W = Wk; out = g_K; }
    else                      { W = Wv; out = g_V; }

    const int t  = threadIdx.x;
    const int tx = t & 15;
    const int ty = t >> 4;
    const int row0 = blockIdx.y * 128;
    const int col0 = blockIdx.x * 128;

    const int aRow = t >> 2;        // 0..63
    const int aCol = (t & 3) * 4;   // 0,4,8,12
    const int bRow = t >> 5;        // 0..7
    const int bCol = (t & 31) * 4;  // 0..124

    float acc[8][8] = {};

    for (int k0 = 0; k0 < D_MODEL; k0 += 16) {
#pragma unroll
        for (int r = 0; r < 2; r++) {
            float4 v = *(const float4*)(x + (size_t)(row0 + aRow + 64 * r) * D_MODEL + k0 + aCol);
            As[aCol + 0][aRow + 64 * r] = v.x;
            As[aCol + 1][aRow + 64 * r] = v.y;
            As[aCol + 2][aRow + 64 * r] = v.z;
            As[aCol + 3][aRow + 64 * r] = v.w;
        }
#pragma unroll
        for (int r = 0; r < 2; r++) {
            float4 v = *(const float4*)(W + (size_t)(k0 + bRow + 8 * r) * D_MODEL + col0 + bCol);
            *(float4*)&Bs[bRow + 8 * r][bCol] = v;
        }
        __syncthreads();

#pragma unroll
        for (int kk = 0; kk < 16; kk++) {
            float4 a0 = *(float4*)&As[kk][ty * 8];
            float4 a1 = *(float4*)&As[kk][ty * 8 + 4];
            float4 b0 = *(float4*)&Bs[kk][tx * 8];
            float4 b1 = *(float4*)&Bs[kk][tx * 8 + 4];
            float a[8] = {a0.x, a0.y, a0.z, a0.w, a1.x, a1.y, a1.z, a1.w};
            float b[8] = {b0.x, b0.y, b0.z, b0.w, b1.x, b1.y, b1.z, b1.w};
#pragma unroll
            for (int i = 0; i < 8; i++)
#pragma unroll
                for (int j = 0; j < 8; j++) acc[i][j] += a[i] * b[j];
        }
        __syncthreads();
    }

#pragma unroll
    for (int i = 0; i < 8; i++) {
        int m = row0 + ty * 8 + i;
#pragma unroll
        for (int j = 0; j < 8; j++) {
            int e = col0 + tx * 8 + j;
            int h = e >> 6;
            out[(size_t)h * (N_TOK * HD) + (size_t)m * HD + (e & 63)] = acc[i][j];
        }
    }
}

// ---------------------------------------------------------------------------
// Causal flash attention: one block per (q-tile of 64, head). 256 threads.
// Online softmax; O accumulator in registers (4x4 per thread).
// ---------------------------------------------------------------------------
__global__ __launch_bounds__(256) void attn_kernel() {
    extern __shared__ float sm[];
    float* Qs   = sm;              // [HD][64] transposed
    float* Ks   = Qs + 64 * 64;    // [HD][64] transposed
    float* Vs   = Ks + 64 * 64;    // [64][HD]
    float* Ss   = Vs + 64 * 64;    // [64][64]
    float* m_s  = Ss + 64 * 64;    // [64]
    float* l_s  = m_s + 64;        // [64]
    float* al_s = l_s + 64;        // [64]

    const int h  = blockIdx.y;
    const int qt = blockIdx.x;
    const int q0 = qt * 64;
    const float* Qg = g_Q + (size_t)h * (N_TOK * HD);
    const float* Kg = g_K + (size_t)h * (N_TOK * HD);
    const float* Vg = g_V + (size_t)h * (N_TOK * HD);

    const int t  = threadIdx.x;
    const int tx = t & 15;
    const int ty = t >> 4;

    // Load Q tile transposed: Qs[d][row]
#pragma unroll
    for (int ff = 0; ff < 4; ff++) {
        int idx = t + 256 * ff;
        int row = idx >> 4;
        int c4  = (idx & 15) * 4;
        float4 v = *(const float4*)(Qg + (size_t)(q0 + row) * HD + c4);
        Qs[(c4 + 0) * 64 + row] = v.x;
        Qs[(c4 + 1) * 64 + row] = v.y;
        Qs[(c4 + 2) * 64 + row] = v.z;
        Qs[(c4 + 3) * 64 + row] = v.w;
    }
    if (t < 64) { m_s[t] = -1e30f; l_s[t] = 0.0f; }

    float o[4][4] = {};

    for (int kt = 0; kt <= qt; kt++) {
        __syncthreads();  // previous iter's reads of Ks/Vs/Ss done
        // Load K (transposed) and V tiles
#pragma unroll
        for (int ff = 0; ff < 4; ff++) {
            int idx = t + 256 * ff;
            int row = idx >> 4;
            int c4  = (idx & 15) * 4;
            float4 kv = *(const float4*)(Kg + (size_t)(kt * 64 + row) * HD + c4);
            Ks[(c4 + 0) * 64 + row] = kv.x;
            Ks[(c4 + 1) * 64 + row] = kv.y;
            Ks[(c4 + 2) * 64 + row] = kv.z;
            Ks[(c4 + 3) * 64 + row] = kv.w;
            float4 vv = *(const float4*)(Vg + (size_t)(kt * 64 + row) * HD + c4);
            *(float4*)&Vs[row * HD + c4] = vv;
        }
        __syncthreads();

        // S = Q K^T  (4x4 per thread)
        float s[4][4] = {};
#pragma unroll
        for (int d = 0; d < HD; d++) {
            float4 a = *(float4*)&Qs[d * 64 + ty * 4];
            float4 b = *(float4*)&Ks[d * 64 + tx * 4];
            float av[4] = {a.x, a.y, a.z, a.w};
            float bv[4] = {b.x, b.y, b.z, b.w};
#pragma unroll
            for (int i = 0; i < 4; i++)
#pragma unroll
                for (int j = 0; j < 4; j++) s[i][j] += av[i] * bv[j];
        }
        const float scale = 0.125f;  // 1/sqrt(64)
        const bool diag = (kt == qt);
#pragma unroll
        for (int i = 0; i < 4; i++) {
            float4 sv;
            float vals[4];
#pragma unroll
            for (int j = 0; j < 4; j++) {
                float v = s[i][j] * scale;
                if (diag && (tx * 4 + j) > (ty * 4 + i)) v = -1e30f;
                vals[j] = v;
            }
            sv.x = vals[0]; sv.y = vals[1]; sv.z = vals[2]; sv.w = vals[3];
            *(float4*)&Ss[(ty * 4 + i) * 64 + tx * 4] = sv;
        }
        __syncthreads();

        // Online softmax: 4 threads per row, 16 cols each
        {
            int row = t >> 2;
            int seg = t & 3;
            float vals[16];
#pragma unroll
            for (int u = 0; u < 4; u++) {
                float4 v = *(float4*)&Ss[row * 64 + seg * 16 + u * 4];
                vals[u * 4 + 0] = v.x; vals[u * 4 + 1] = v.y;
                vals[u * 4 + 2] = v.z; vals[u * 4 + 3] = v.w;
            }
            float mx = vals[0];
#pragma unroll
            for (int u = 1; u < 16; u++) mx = fmaxf(mx, vals[u]);
            mx = fmaxf(mx, __shfl_xor_sync(0xffffffffu, mx, 1));
            mx = fmaxf(mx, __shfl_xor_sync(0xffffffffu, mx, 2));
            float m_old = m_s[row];
            float m_new = fmaxf(m_old, mx);
            float sum = 0.0f;
#pragma unroll
            for (int u = 0; u < 16; u++) {
                float p = __expf(vals[u] - m_new);
                vals[u] = p;
                sum += p;
            }
#pragma unroll
            for (int u = 0; u < 4; u++) {
                float4 v;
                v.x = vals[u * 4 + 0]; v.y = vals[u * 4 + 1];
                v.z = vals[u * 4 + 2]; v.w = vals[u * 4 + 3];
                *(float4*)&Ss[row * 64 + seg * 16 + u * 4] = v;
            }
            sum += __shfl_xor_sync(0xffffffffu, sum, 1);
            sum += __shfl_xor_sync(0xffffffffu, sum, 2);
            if (seg == 0) {
                float alpha = __expf(m_old - m_new);
                l_s[row]  = l_s[row] * alpha + sum;
                m_s[row]  = m_new;
                al_s[row] = alpha;
            }
        }
        __syncthreads();

        // Rescale O and accumulate P @ V
        float alpha_r[4];
#pragma unroll
        for (int i = 0; i < 4; i++) alpha_r[i] = al_s[ty * 4 + i];
#pragma unroll
        for (int i = 0; i < 4; i++)
#pragma unroll
            for (int j = 0; j < 4; j++) o[i][j] *= alpha_r[i];

#pragma unroll
        for (int k = 0; k < 64; k++) {
            float p[4];
#pragma unroll
            for (int i = 0; i < 4; i++) p[i] = Ss[(ty * 4 + i) * 64 + k];
            float4 vv = *(float4*)&Vs[k * HD + tx * 4];
            float bv[4] = {vv.x, vv.y, vv.z, vv.w};
#pragma unroll
            for (int i = 0; i < 4; i++)
#pragma unroll
                for (int j = 0; j < 4; j++) o[i][j] += p[i] * bv[j];
        }
    }

    // Epilogue: normalize and write ctx head-major
    float inv[4];
#pragma unroll
    for (int i = 0; i < 4; i++) inv[i] = 1.0f / l_s[ty * 4 + i];
#pragma unroll
    for (int i = 0; i < 4; i++) {
        float4 v;
        v.x = o[i][0] * inv[i]; v.y = o[i][1] * inv[i];
        v.z = o[i][2] * inv[i]; v.w = o[i][3] * inv[i];
        *(float4*)&g_C[(size_t)h * (N_TOK * HD) + (size_t)(q0 + ty * 4 + i) * HD + tx * 4] = v;
    }
}

// ---------------------------------------------------------------------------
// Output projection: out[m,e] = sum_k ctx(m,k) * Wo[k,e] + bo[e]
// ctx(m,k) read from head-major g_C: head = k>>6, offset = k&63.
// ---------------------------------------------------------------------------
__global__ __launch_bounds__(256) void oproj_gemm(const float* __restrict__ Wo,
                                                  const float* __restrict__ bo,
                                                  float* __restrict__ out) {
    __shared__ float As[16][128];
    __shared__ float Bs[16][128];

    const int t  = threadIdx.x;
    const int tx = t & 15;
    const int ty = t >> 4;
    const int row0 = blockIdx.y * 128;
    const int col0 = blockIdx.x * 128;

    const int aRow = t >> 2;
    const int aCol = (t & 3) * 4;
    const int bRow = t >> 5;
    const int bCol = (t & 31) * 4;

    float acc[8][8] = {};

    for (int k0 = 0; k0 < D_MODEL; k0 += 16) {
        const int head = k0 >> 6;
        const int off  = k0 & 63;
        const float* Abase = g_C + (size_t)head * (N_TOK * HD);
#pragma unroll
        for (int r = 0; r < 2; r++) {
            float4 v = *(const float4*)(Abase + (size_t)(row0 + aRow + 64 * r) * HD + off + aCol);
            As[aCol + 0][aRow + 64 * r] = v.x;
            As[aCol + 1][aRow + 64 * r] = v.y;
            As[aCol + 2][aRow + 64 * r] = v.z;
            As[aCol + 3][aRow + 64 * r] = v.w;
        }
#pragma unroll
        for (int r = 0; r < 2; r++) {
            float4 v = *(const float4*)(Wo + (size_t)(k0 + bRow + 8 * r) * D_MODEL + col0 + bCol);
            *(float4*)&Bs[bRow + 8 * r][bCol] = v;
        }
        __syncthreads();

#pragma unroll
        for (int kk = 0; kk < 16; kk++) {
            float4 a0 = *(float4*)&As[kk][ty * 8];
            float4 a1 = *(float4*)&As[kk][ty * 8 + 4];
            float4 b0 = *(float4*)&Bs[kk][tx * 8];
            float4 b1 = *(float4*)&Bs[kk][tx * 8 + 4];
            float a[8] = {a0.x, a0.y, a0.z, a0.w, a1.x, a1.y, a1.z, a1.w};
            float b[8] = {b0.x, b0.y, b0.z, b0.w, b1.x, b1.y, b1.z, b1.w};
#pragma unroll
            for (int i = 0; i < 8; i++)
#pragma unroll
                for (int j = 0; j < 8; j++) acc[i][j] += a[i] * b[j];
        }
        __syncthreads();
    }

#pragma unroll
    for (int i = 0; i < 8; i++) {
        int m = row0 + ty * 8 + i;
#pragma unroll
        for (int j = 0; j < 8; j++) {
            int e = col0 + tx * 8 + j;
            out[(size_t)m * D_MODEL + e] = acc[i][j] + bo[e];
        }
    }
}

extern "C" void kernel_launch(void* const* d_in, const int* in_sizes, int n_in,
                              void* d_out, int out_size) {
    const float* x  = (const float*)d_in[0];
    const float* Wq = (const float*)d_in[1];
    const float* Wk = (const float*)d_in[2];
    const float* Wv = (const float*)d_in[3];
    const float* Wo = (const float*)d_in[4];
    const float* bo = (const float*)d_in[5];
    float* out = (float*)d_out;

    const int attn_smem = (4 * 64 * 64 + 3 * 64) * (int)sizeof(float);  // ~66 KB
    cudaFuncSetAttribute(attn_kernel, cudaFuncAttributeMaxDynamicSharedMemorySize, attn_smem);

    qkv_gemm<<<dim3(8, 32, 3), 256>>>(x, Wq, Wk, Wv);
    attn_kernel<<<dim3(N_TOK / 64, NH), 256, attn_smem>>>();
    oproj_gemm<<<dim3(8, 32), 256>>>(Wo, bo, out);
}

// round 2
// speedup vs baseline: 1.1683x; 1.1683x over previous
#include <cuda_runtime.h>

#define N_TOK 4096
#define D_MODEL 1024
#define NH 16
#define HD 64

// Scratch (head-major [H][N][HD]) — __device__ globals, no allocation.
__device__ float g_Q[NH * N_TOK * HD];
__device__ float g_K[NH * N_TOK * HD];
__device__ float g_V[NH * N_TOK * HD];
__device__ float g_C[NH * N_TOK * HD];

// Fast exp on the FMA pipe (no MUFU): exp(x) = 2^(x*log2e), x <= 0 expected.
// Round-to-nearest via magic constant, degree-5 poly on f in [-0.5, 0.5],
// exponent injected via integer add. rel err ~3e-6.
__device__ __forceinline__ float fast_exp(float x) {
    float y = fmaxf(x * 1.4426950408889634f, -126.0f);
    float t = y + 12582912.0f;                       // 1.5 * 2^23
    int   i = __float_as_int(t) - 0x4B400000;        // integer part of y
    float f = y - (t - 12582912.0f);                 // f in [-0.5, 0.5]
    float p =            1.3333558146e-3f;
    p = fmaf(p, f, 9.6181291057e-3f);
    p = fmaf(p, f, 5.5504108664e-2f);
    p = fmaf(p, f, 2.4022650696e-1f);
    p = fmaf(p, f, 6.9314718056e-1f);
    p = fmaf(p, f, 1.0f);
    return __int_as_float(__float_as_int(p) + (i << 23));
}

// ---------------------------------------------------------------------------
// QKV projection: C[m,e] = sum_k x[m,k] * W[k,e], written head-major.
// 128x128x16 tiles, 8x8 per thread, 256 threads. grid.z selects Wq/Wk/Wv.
// ---------------------------------------------------------------------------
__global__ __launch_bounds__(256) void qkv_gemm(const float* __restrict__ x,
                                                const float* __restrict__ Wq,
                                                const float* __restrict__ Wk,
                                                const float* __restrict__ Wv) {
    __shared__ float As[16][128];
    __shared__ float Bs[16][128];

    const float* W;
    float* out;
    if (blockIdx.z == 0)      { W = Wq; out = g_Q; }
    else if (blockIdx.z == 1) { W = Wk; out = g_K; }
    else                      { W = Wv; out = g_V; }

    const int t  = threadIdx.x;
    const int tx = t & 15;
    const int ty = t >> 4;
    const int row0 = blockIdx.y * 128;
    const int col0 = blockIdx.x * 128;

    const int aRow = t >> 2;        // 0..63
    const int aCol = (t & 3) * 4;   // 0,4,8,12
    const int bRow = t >> 5;        // 0..7
    const int bCol = (t & 31) * 4;  // 0..124

    float acc[8][8] = {};

    for (int k0 = 0; k0 < D_MODEL; k0 += 16) {
#pragma unroll
        for (int r = 0; r < 2; r++) {
            float4 v = *(const float4*)(x + (size_t)(row0 + aRow + 64 * r) * D_MODEL + k0 + aCol);
            As[aCol + 0][aRow + 64 * r] = v.x;
            As[aCol + 1][aRow + 64 * r] = v.y;
            As[aCol + 2][aRow + 64 * r] = v.z;
            As[aCol + 3][aRow + 64 * r] = v.w;
        }
#pragma unroll
        for (int r = 0; r < 2; r++) {
            float4 v = *(const float4*)(W + (size_t)(k0 + bRow + 8 * r) * D_MODEL + col0 + bCol);
            *(float4*)&Bs[bRow + 8 * r][bCol] = v;
        }
        __syncthreads();

#pragma unroll
        for (int kk = 0; kk < 16; kk++) {
            float4 a0 = *(float4*)&As[kk][ty * 8];
            float4 a1 = *(float4*)&As[kk][ty * 8 + 4];
            float4 b0 = *(float4*)&Bs[kk][tx * 8];
            float4 b1 = *(float4*)&Bs[kk][tx * 8 + 4];
            float a[8] = {a0.x, a0.y, a0.z, a0.w, a1.x, a1.y, a1.z, a1.w};
            float b[8] = {b0.x, b0.y, b0.z, b0.w, b1.x, b1.y, b1.z, b1.w};
#pragma unroll
            for (int i = 0; i < 8; i++)
#pragma unroll
                for (int j = 0; j < 8; j++) acc[i][j] += a[i] * b[j];
        }
        __syncthreads();
    }

#pragma unroll
    for (int i = 0; i < 8; i++) {
        int m = row0 + ty * 8 + i;
#pragma unroll
        for (int j = 0; j < 8; j++) {
            int e = col0 + tx * 8 + j;
            int h = e >> 6;
            out[(size_t)h * (N_TOK * HD) + (size_t)m * HD + (e & 63)] = acc[i][j];
        }
    }
}

// ---------------------------------------------------------------------------
// Causal flash attention: one block per (q-tile of 128, head). 256 threads.
// 128x128 S tile, 8x8 register blocking (split halves: tx*4 and 64+tx*4).
// Online softmax with polynomial exp (no MUFU). O accumulator 8x4 in regs.
// ---------------------------------------------------------------------------
#define QK_STR 132   // padded row stride (floats) for Qs/Ks/Ss
#define ATTN_SMEM ((2 * 64 * QK_STR + 128 * 64 + 128 * QK_STR + 3 * 128) * 4)

__global__ __launch_bounds__(256) void attn_kernel() {
    extern __shared__ float sm[];
    float* Qs   = sm;                       // [64][132]  (d-major, transposed)
    float* Ks   = Qs + 64 * QK_STR;         // [64][132]
    float* Vs   = Ks + 64 * QK_STR;         // [128][64]  (row-major)
    float* Ss   = Vs + 128 * 64;            // [128][132]
    float* m_s  = Ss + 128 * QK_STR;        // [128]
    float* l_s  = m_s + 128;                // [128]
    float* al_s = l_s + 128;                // [128]

    const int h  = blockIdx.y;
    const int qt = (int)(gridDim.x - 1 - blockIdx.x);  // big tiles first
    const int q0 = qt * 128;
    const float* Qg = g_Q + (size_t)h * (N_TOK * HD);
    const float* Kg = g_K + (size_t)h * (N_TOK * HD);
    const float* Vg = g_V + (size_t)h * (N_TOK * HD);

    const int t  = threadIdx.x;
    const int tx = t & 15;
    const int ty = t >> 4;
    const int dl = t & 63;   // d-lane for transposed loads
    const int tl = t >> 6;   // token-lane 0..3

    // Load Q tile transposed: Qs[d][tok]
#pragma unroll
    for (int tt = 0; tt < 128; tt += 4)
        Qs[dl * QK_STR + tt + tl] = Qg[(size_t)(q0 + tt + tl) * HD + dl];
    if (t < 128) { m_s[t] = -1e30f; l_s[t] = 0.0f; }

    int row_r[8];
#pragma unroll
    for (int i = 0; i < 8; i++) row_r[i] = (i < 4) ? (ty * 4 + i) : (64 + ty * 4 + (i - 4));
    const int colA = tx * 4;
    const int colB = 64 + tx * 4;

    float o[8][4] = {};

    for (int kt = 0; kt <= qt; kt++) {
        __syncthreads();  // prev iter's PV reads done
        const int k0 = kt * 128;
        // K transposed, V row-major
#pragma unroll
        for (int tt = 0; tt < 128; tt += 4)
            Ks[dl * QK_STR + tt + tl] = Kg[(size_t)(k0 + tt + tl) * HD + dl];
#pragma unroll
        for (int ff = 0; ff < 8; ff++) {
            int idx = t + 256 * ff;
            int r = idx >> 4, c4 = (idx & 15) * 4;
            *(float4*)&Vs[r * 64 + c4] = *(const float4*)(Vg + (size_t)(k0 + r) * HD + c4);
        }
        __syncthreads();

        // S = Q K^T  (8x8 per thread, split halves)
        float s[8][8] = {};
#pragma unroll 4
        for (int d = 0; d < HD; d++) {
            float4 a0 = *(float4*)&Qs[d * QK_STR + ty * 4];
            float4 a1 = *(float4*)&Qs[d * QK_STR + 64 + ty * 4];
            float4 b0 = *(float4*)&Ks[d * QK_STR + tx * 4];
            float4 b1 = *(float4*)&Ks[d * QK_STR + 64 + tx * 4];
            float a[8] = {a0.x, a0.y, a0.z, a0.w, a1.x, a1.y, a1.z, a1.w};
            float b[8] = {b0.x, b0.y, b0.z, b0.w, b1.x, b1.y, b1.z, b1.w};
#pragma unroll
            for (int i = 0; i < 8; i++)
#pragma unroll
                for (int j = 0; j < 8; j++) s[i][j] += a[i] * b[j];
        }

        // scale + causal mask + store to Ss
        const float scale = 0.125f;  // 1/sqrt(64)
        const bool diag = (kt == qt);
#pragma unroll
        for (int i = 0; i < 8; i++) {
            const int rg = row_r[i];
            float4 v0, v1;
            float w0[4], w1[4];
#pragma unroll
            for (int j = 0; j < 4; j++) {
                float vA = s[i][j] * scale;
                float vB = s[i][j + 4] * scale;
                if (diag && (colA + j) > rg) vA = -1e30f;
                if (diag && (colB + j) > rg) vB = -1e30f;
                w0[j] = vA; w1[j] = vB;
            }
            v0.x = w0[0]; v0.y = w0[1]; v0.z = w0[2]; v0.w = w0[3];
            v1.x = w1[0]; v1.y = w1[1]; v1.z = w1[2]; v1.w = w1[3];
            *(float4*)&Ss[rg * QK_STR + colA] = v0;
            *(float4*)&Ss[rg * QK_STR + colB] = v1;
        }
        __syncthreads();

        // Online softmax: 2 threads per row, 64 cols each
        {
            const int row  = t >> 1;
            const int half = t & 1;
            float* Sr = Ss + row * QK_STR + half * 64;
            float mx = -1e30f;
#pragma unroll
            for (int u = 0; u < 16; u++) {
                float4 v = *(float4*)&Sr[u * 4];
                mx = fmaxf(mx, fmaxf(fmaxf(v.x, v.y), fmaxf(v.z, v.w)));
            }
            mx = fmaxf(mx, __shfl_xor_sync(0xffffffffu, mx, 1));
            float m_old = m_s[row];
            float m_new = fmaxf(m_old, mx);
            float sum = 0.0f;
#pragma unroll
            for (int u = 0; u < 16; u++) {
                float4 v = *(float4*)&Sr[u * 4];
                v.x = fast_exp(v.x - m_new);
                v.y = fast_exp(v.y - m_new);
                v.z = fast_exp(v.z - m_new);
                v.w = fast_exp(v.w - m_new);
                *(float4*)&Sr[u * 4] = v;
                sum += (v.x + v.y) + (v.z + v.w);
            }
            sum += __shfl_xor_sync(0xffffffffu, sum, 1);
            if (half == 0) {
                float alpha = fast_exp(m_old - m_new);
                l_s[row]  = l_s[row] * alpha + sum;
                m_s[row]  = m_new;
                al_s[row] = alpha;
            }
        }
        __syncthreads();

        // Rescale O; accumulate O += P @ V  (k unrolled by 4, float4 P loads)
        float al[8];
#pragma unroll
        for (int i = 0; i < 8; i++) al[i] = al_s[row_r[i]];
#pragma unroll
        for (int i = 0; i < 8; i++)
#pragma unroll
            for (int j = 0; j < 4; j++) o[i][j] *= al[i];

#pragma unroll 2
        for (int k = 0; k < 128; k += 4) {
            float4 p[8];
#pragma unroll
            for (int i = 0; i < 8; i++) p[i] = *(float4*)&Ss[row_r[i] * QK_STR + k];
            float4 vv[4];
#pragma unroll
            for (int u = 0; u < 4; u++) vv[u] = *(float4*)&Vs[(k + u) * 64 + tx * 4];
#pragma unroll
            for (int i = 0; i < 8; i++) {
                float pk[4] = {p[i].x, p[i].y, p[i].z, p[i].w};
#pragma unroll
                for (int u = 0; u < 4; u++) {
                    o[i][0] = fmaf(pk[u], vv[u].x, o[i][0]);
                    o[i][1] = fmaf(pk[u], vv[u].y, o[i][1]);
                    o[i][2] = fmaf(pk[u], vv[u].z, o[i][2]);
                    o[i][3] = fmaf(pk[u], vv[u].w, o[i][3]);
                }
            }
        }
    }

    // Epilogue: normalize and write ctx head-major
#pragma unroll
    for (int i = 0; i < 8; i++) {
        float inv = 1.0f / l_s[row_r[i]];
        float4 v;
        v.x = o[i][0] * inv; v.y = o[i][1] * inv;
        v.z = o[i][2] * inv; v.w = o[i][3] * inv;
        *(float4*)&g_C[(size_t)h * (N_TOK * HD) + (size_t)(q0 + row_r[i]) * HD + tx * 4] = v;
    }
}

// ---------------------------------------------------------------------------
// Output projection: out[m,e] = sum_k ctx(m,k) * Wo[k,e] + bo[e]
// ctx(m,k) read from head-major g_C: head = k>>6, offset = k&63.
// ---------------------------------------------------------------------------
__global__ __launch_bounds__(256) void oproj_gemm(const float* __restrict__ Wo,
                                                  const float* __restrict__ bo,
                                                  float* __restrict__ out) {
    __shared__ float As[16][128];
    __shared__ float Bs[16][128];

    const int t  = threadIdx.x;
    const int tx = t & 15;
    const int ty = t >> 4;
    const int row0 = blockIdx.y * 128;
    const int col0 = blockIdx.x * 128;

    const int aRow = t >> 2;
    const int aCol = (t & 3) * 4;
    const int bRow = t >> 5;
    const int bCol = (t & 31) * 4;

    float acc[8][8] = {};

    for (int k0 = 0; k0 < D_MODEL; k0 += 16) {
        const int head = k0 >> 6;
        const int off  = k0 & 63;
        const float* Abase = g_C + (size_t)head * (N_TOK * HD);
#pragma unroll
        for (int r = 0; r < 2; r++) {
            float4 v = *(const float4*)(Abase + (size_t)(row0 + aRow + 64 * r) * HD + off + aCol);
            As[aCol + 0][aRow + 64 * r] = v.x;
            As[aCol + 1][aRow + 64 * r] = v.y;
            As[aCol + 2][aRow + 64 * r] = v.z;
            As[aCol + 3][aRow + 64 * r] = v.w;
        }
#pragma unroll
        for (int r = 0; r < 2; r++) {
            float4 v = *(const float4*)(Wo + (size_t)(k0 + bRow + 8 * r) * D_MODEL + col0 + bCol);
            *(float4*)&Bs[bRow + 8 * r][bCol] = v;
        }
        __syncthreads();

#pragma unroll
        for (int kk = 0; kk < 16; kk++) {
            float4 a0 = *(float4*)&As[kk][ty * 8];
            float4 a1 = *(float4*)&As[kk][ty * 8 + 4];
            float4 b0 = *(float4*)&Bs[kk][tx * 8];
            float4 b1 = *(float4*)&Bs[kk][tx * 8 + 4];
            float a[8] = {a0.x, a0.y, a0.z, a0.w, a1.x, a1.y, a1.z, a1.w};
            float b[8] = {b0.x, b0.y, b0.z, b0.w, b1.x, b1.y, b1.z, b1.w};
#pragma unroll
            for (int i = 0; i < 8; i++)
#pragma unroll
                for (int j = 0; j < 8; j++) acc[i][j] += a[i] * b[j];
        }
        __syncthreads();
    }

#pragma unroll
    for (int i = 0; i < 8; i++) {
        int m = row0 + ty * 8 + i;
#pragma unroll
        for (int j = 0; j < 8; j++) {
            int e = col0 + tx * 8 + j;
            out[(size_t)m * D_MODEL + e] = acc[i][j] + bo[e];
        }
    }
}

extern "C" void kernel_launch(void* const* d_in, const int* in_sizes, int n_in,
                              void* d_out, int out_size) {
    const float* x  = (const float*)d_in[0];
    const float* Wq = (const float*)d_in[1];
    const float* Wk = (const float*)d_in[2];
    const float* Wv = (const float*)d_in[3];
    const float* Wo = (const float*)d_in[4];
    const float* bo = (const float*)d_in[5];
    float* out = (float*)d_out;

    cudaFuncSetAttribute(attn_kernel, cudaFuncAttributeMaxDynamicSharedMemorySize, ATTN_SMEM);

    qkv_gemm<<<dim3(8, 32, 3), 256>>>(x, Wq, Wk, Wv);
    attn_kernel<<<dim3(N_TOK / 128, NH), 256, ATTN_SMEM>>>();
    oproj_gemm<<<dim3(8, 32), 256>>>(Wo, bo, out);
}

// round 4
// speedup vs baseline: 1.5299x; 1.3096x over previous
#include <cuda_runtime.h>
#include <cuda_bf16.h>
#include <cstdint>

#define N_TOK 4096
#define D_MODEL 1024
#define NH 16
#define HD 64

// ---------------------------------------------------------------------------
// Scratch (__device__ globals — no allocation).
// ---------------------------------------------------------------------------
__device__ float g_Q[NH * N_TOK * HD];
__device__ float g_K[NH * N_TOK * HD];
__device__ float g_V[NH * N_TOK * HD];
__device__ __nv_bfloat16 g_x_hi[N_TOK * D_MODEL];
__device__ __nv_bfloat16 g_x_lo[N_TOK * D_MODEL];
__device__ __nv_bfloat16 g_WT_hi[4 * D_MODEL * D_MODEL];  // [which][e][k]
__device__ __nv_bfloat16 g_WT_lo[4 * D_MODEL * D_MODEL];
__device__ __nv_bfloat16 g_C_hi[NH * N_TOK * HD];          // ctx head-major
__device__ __nv_bfloat16 g_C_lo[NH * N_TOK * HD];

// HMMA m16n8k16 bf16 -> f32 accum (baseline PTX, works on sm_103 target)
__device__ __forceinline__ void mma_bf16(float* d, const uint32_t* a, const uint32_t* b) {
    asm volatile(
        "mma.sync.aligned.m16n8k16.row.col.f32.bf16.bf16.f32 "
        "{%0,%1,%2,%3}, {%4,%5,%6,%7}, {%8,%9}, {%0,%1,%2,%3};"
        : "+f"(d[0]), "+f"(d[1]), "+f"(d[2]), "+f"(d[3])
        : "r"(a[0]), "r"(a[1]), "r"(a[2]), "r"(a[3]), "r"(b[0]), "r"(b[1]));
}

// Fast exp on the FMA pipe (no MUFU). rel err ~3e-6.
__device__ __forceinline__ float fast_exp(float x) {
    float y = fmaxf(x * 1.4426950408889634f, -126.0f);
    float t = y + 12582912.0f;
    int   i = __float_as_int(t) - 0x4B400000;
    float f = y - (t - 12582912.0f);
    float p =            1.3333558146e-3f;
    p = fmaf(p, f, 9.6181291057e-3f);
    p = fmaf(p, f, 5.5504108664e-2f);
    p = fmaf(p, f, 2.4022650696e-1f);
    p = fmaf(p, f, 6.9314718056e-1f);
    p = fmaf(p, f, 1.0f);
    return __int_as_float(__float_as_int(p) + (i << 23));
}

// ---------------------------------------------------------------------------
// Prep: split x into bf16 hi/lo (K-major, same layout as x).
// ---------------------------------------------------------------------------
__global__ __launch_bounds__(256) void split_x(const float* __restrict__ x) {
    int idx = blockIdx.x * 256 + threadIdx.x;      // float4 index, 1M total
    float4 v = ((const float4*)x)[idx];
    __nv_bfloat162 h0 = __floats2bfloat162_rn(v.x, v.y);
    __nv_bfloat162 h1 = __floats2bfloat162_rn(v.z, v.w);
    float l0 = v.x - __low2float(h0), l1 = v.y - __high2float(h0);
    float l2 = v.z - __low2float(h1), l3 = v.w - __high2float(h1);
    __nv_bfloat162 e0 = __floats2bfloat162_rn(l0, l1);
    __nv_bfloat162 e1 = __floats2bfloat162_rn(l2, l3);
    ((__nv_bfloat162*)g_x_hi)[idx * 2]     = h0;
    ((__nv_bfloat162*)g_x_hi)[idx * 2 + 1] = h1;
    ((__nv_bfloat162*)g_x_lo)[idx * 2]     = e0;
    ((__nv_bfloat162*)g_x_lo)[idx * 2 + 1] = e1;
}

// ---------------------------------------------------------------------------
// Prep: WT[which][e][k] = W[k][e], split into bf16 hi/lo. 32x32 smem transpose.
// ---------------------------------------------------------------------------
__global__ void wprep(const float* __restrict__ Wq, const float* __restrict__ Wk,
                      const float* __restrict__ Wv, const float* __restrict__ Wo) {
    const int z = blockIdx.z;
    const float* W = (z == 0) ? Wq : (z == 1) ? Wk : (z == 2) ? Wv : Wo;
    __shared__ float ts[32][33];
    const int e0 = blockIdx.x * 32, k0 = blockIdx.y * 32;
    const int tx = threadIdx.x, ty = threadIdx.y;  // (32, 8)
#pragma unroll
    for (int i = 0; i < 4; i++)
        ts[ty + 8 * i][tx] = W[(size_t)(k0 + ty + 8 * i) * D_MODEL + e0 + tx];
    __syncthreads();
#pragma unroll
    for (int i = 0; i < 4; i++) {
        int row = ty + 8 * i;
        float v = ts[tx][row];
        __nv_bfloat16 hi = __float2bfloat16(v);
        float lo = v - __bfloat162float(hi);
        size_t o = (size_t)z * (D_MODEL * D_MODEL) + (size_t)(e0 + row) * D_MODEL + k0 + tx;
        g_WT_hi[o] = hi;
        g_WT_lo[o] = __float2bfloat16(lo);
    }
}

// ---------------------------------------------------------------------------
// HMMA bf16-split GEMM: D[128x128] = A[128xK] @ B^T (B = WT[e][k], K-major).
// 8 warps (2x4), 64x32 per warp, m16n8k16 fragments, K chunks of 32.
// mode 0: qkv (z picks Wq/Wk/Wv; A = x hi/lo; out scatter head-major fp32)
// mode 1: oproj (A = ctx hi/lo head-major; out = d_out + bias)
// ---------------------------------------------------------------------------
#define KC 32
#define ASTR 40  // bf16 elems per smem row (80 B: 16B-aligned, conflict-free LDS)

__global__ __launch_bounds__(256, 2) void mma_gemm(int mode, float* __restrict__ out,
                                                   const float* __restrict__ bo) {
    __shared__ __nv_bfloat16 sAh[128 * ASTR];
    __shared__ __nv_bfloat16 sAl[128 * ASTR];
    __shared__ __nv_bfloat16 sBh[128 * ASTR];
    __shared__ __nv_bfloat16 sBl[128 * ASTR];

    const int t = threadIdx.x;
    const int wid = t >> 5, lane = t & 31;
    const int wm = wid & 1, wn = wid >> 1;      // warp grid 2 x 4
    const int g = lane >> 2, tig = lane & 3;
    const int row0 = blockIdx.y * 128;
    const int col0 = blockIdx.x * 128;
    const int which = (mode == 0) ? blockIdx.z : 3;

    const __nv_bfloat16* Bh_g = g_WT_hi + (size_t)which * (D_MODEL * D_MODEL) + (size_t)col0 * D_MODEL;
    const __nv_bfloat16* Bl_g = g_WT_lo + (size_t)which * (D_MODEL * D_MODEL) + (size_t)col0 * D_MODEL;

    float acc[4][4][4] = {};   // [mt][nt][frag]

    for (int kc = 0; kc < D_MODEL / KC; kc++) {
        const int k0 = kc * KC;
        const __nv_bfloat16 *Ah_g, *Al_g;
        int astr;
        if (mode == 0) {
            Ah_g = g_x_hi + (size_t)row0 * D_MODEL + k0;
            Al_g = g_x_lo + (size_t)row0 * D_MODEL + k0;
            astr = D_MODEL;
        } else {
            size_t base = (size_t)(k0 >> 6) * (N_TOK * HD) + (size_t)row0 * HD + (k0 & 63);
            Ah_g = g_C_hi + base;
            Al_g = g_C_lo + base;
            astr = HD;
        }
        // Load chunk: 4 tiles x 512 uint4; 2 uint4 per thread per tile.
#pragma unroll
        for (int i = 0; i < 2; i++) {
            int idx = t + 256 * i;
            int r = idx >> 2, c = (idx & 3) * 8;       // 8 bf16 per uint4
            int so = r * ASTR + c;
            *(uint4*)&sAh[so] = *(const uint4*)(Ah_g + (size_t)r * astr + c);
            *(uint4*)&sAl[so] = *(const uint4*)(Al_g + (size_t)r * astr + c);
            *(uint4*)&sBh[so] = *(const uint4*)(Bh_g + (size_t)r * D_MODEL + k0 + c);
            *(uint4*)&sBl[so] = *(const uint4*)(Bl_g + (size_t)r * D_MODEL + k0 + c);
        }
        __syncthreads();

#pragma unroll
        for (int ks = 0; ks < KC; ks += 16) {
            // B fragments for all 4 n-tiles (hi + lo)
            uint32_t bh[4][2], bl[4][2];
#pragma unroll
            for (int nt = 0; nt < 4; nt++) {
                int n0 = wn * 32 + nt * 8 + g;
                bh[nt][0] = *(uint32_t*)&sBh[n0 * ASTR + ks + 2 * tig];
                bh[nt][1] = *(uint32_t*)&sBh[n0 * ASTR + ks + 8 + 2 * tig];
                bl[nt][0] = *(uint32_t*)&sBl[n0 * ASTR + ks + 2 * tig];
                bl[nt][1] = *(uint32_t*)&sBl[n0 * ASTR + ks + 8 + 2 * tig];
            }
#pragma unroll
            for (int mt = 0; mt < 4; mt++) {
                int r0 = wm * 64 + mt * 16 + g;
                uint32_t ah[4], al[4];
                ah[0] = *(uint32_t*)&sAh[r0 * ASTR + ks + 2 * tig];
                ah[1] = *(uint32_t*)&sAh[(r0 + 8) * ASTR + ks + 2 * tig];
                ah[2] = *(uint32_t*)&sAh[r0 * ASTR + ks + 8 + 2 * tig];
                ah[3] = *(uint32_t*)&sAh[(r0 + 8) * ASTR + ks + 8 + 2 * tig];
                al[0] = *(uint32_t*)&sAl[r0 * ASTR + ks + 2 * tig];
                al[1] = *(uint32_t*)&sAl[(r0 + 8) * ASTR + ks + 2 * tig];
                al[2] = *(uint32_t*)&sAl[r0 * ASTR + ks + 8 + 2 * tig];
                al[3] = *(uint32_t*)&sAl[(r0 + 8) * ASTR + ks + 8 + 2 * tig];
#pragma unroll
                for (int nt = 0; nt < 4; nt++) {
                    mma_bf16(acc[mt][nt], ah, bh[nt]);   // hi*hi
                    mma_bf16(acc[mt][nt], ah, bl[nt]);   // hi*lo
                    mma_bf16(acc[mt][nt], al, bh[nt]);   // lo*hi
                }
            }
        }
        __syncthreads();
    }

    // Epilogue: accums are (row g / g+8, cols 2tig, 2tig+1) per frag.
    if (mode == 0) {
        float* q = (which == 0) ? g_Q : (which == 1) ? g_K : g_V;
        const int head = (col0 + wn * 32) >> 6;     // constant per warp
        float* base = q + (size_t)head * (N_TOK * HD);
#pragma unroll
        for (int mt = 0; mt < 4; mt++) {
            int m = row0 + wm * 64 + mt * 16 + g;
#pragma unroll
            for (int nt = 0; nt < 4; nt++) {
                int eh = (wn * 32 + nt * 8 + 2 * tig) & 63;
                *(float2*)(base + (size_t)m * HD + eh)       = make_float2(acc[mt][nt][0], acc[mt][nt][1]);
                *(float2*)(base + (size_t)(m + 8) * HD + eh) = make_float2(acc[mt][nt][2], acc[mt][nt][3]);
            }
        }
    } else {
#pragma unroll
        for (int mt = 0; mt < 4; mt++) {
            int m = row0 + wm * 64 + mt * 16 + g;
#pragma unroll
            for (int nt = 0; nt < 4; nt++) {
                int e = col0 + wn * 32 + nt * 8 + 2 * tig;
                float2 b = *(const float2*)(bo + e);
                *(float2*)(out + (size_t)m * D_MODEL + e) =
                    make_float2(acc[mt][nt][0] + b.x, acc[mt][nt][1] + b.y);
                *(float2*)(out + (size_t)(m + 8) * D_MODEL + e) =
                    make_float2(acc[mt][nt][2] + b.x, acc[mt][nt][3] + b.y);
            }
        }
    }
}

// ---------------------------------------------------------------------------
// Causal flash attention: 128x128 tiles, poly exp, fp32 FFMA core.
// Epilogue writes ctx as bf16 hi/lo head-major for the oproj MMA.
// ---------------------------------------------------------------------------
#define QK_STR 132
#define ATTN_SMEM ((2 * 64 * QK_STR + 128 * 64 + 128 * QK_STR + 3 * 128) * 4)

__global__ __launch_bounds__(256) void attn_kernel() {
    extern __shared__ float smf[];
    float* Qs   = smf;
    float* Ks   = Qs + 64 * QK_STR;
    float* Vs   = Ks + 64 * QK_STR;
    float* Ss   = Vs + 128 * 64;
    float* m_s  = Ss + 128 * QK_STR;
    float* l_s  = m_s + 128;
    float* al_s = l_s + 128;

    const int h  = blockIdx.y;
    const int qt = (int)(gridDim.x - 1 - blockIdx.x);
    const int q0 = qt * 128;
    const float* Qg = g_Q + (size_t)h * (N_TOK * HD);
    const float* Kg = g_K + (size_t)h * (N_TOK * HD);
    const float* Vg = g_V + (size_t)h * (N_TOK * HD);

    const int t  = threadIdx.x;
    const int tx = t & 15;
    const int ty = t >> 4;
    const int dl = t & 63;
    const int tl = t >> 6;

#pragma unroll
    for (int tt = 0; tt < 128; tt += 4)
        Qs[dl * QK_STR + tt + tl] = Qg[(size_t)(q0 + tt + tl) * HD + dl];
    if (t < 128) { m_s[t] = -1e30f; l_s[t] = 0.0f; }

    int row_r[8];
#pragma unroll
    for (int i = 0; i < 8; i++) row_r[i] = (i < 4) ? (ty * 4 + i) : (64 + ty * 4 + (i - 4));
    const int colA = tx * 4;
    const int colB = 64 + tx * 4;

    float o[8][4] = {};

    for (int kt = 0; kt <= qt; kt++) {
        __syncthreads();
        const int k0 = kt * 128;
#pragma unroll
        for (int tt = 0; tt < 128; tt += 4)
            Ks[dl * QK_STR + tt + tl] = Kg[(size_t)(k0 + tt + tl) * HD + dl];
#pragma unroll
        for (int ff = 0; ff < 8; ff++) {
            int idx = t + 256 * ff;
            int r = idx >> 4, c4 = (idx & 15) * 4;
            *(float4*)&Vs[r * 64 + c4] = *(const float4*)(Vg + (size_t)(k0 + r) * HD + c4);
        }
        __syncthreads();

        float s[8][8] = {};
#pragma unroll 4
        for (int d = 0; d < HD; d++) {
            float4 a0 = *(float4*)&Qs[d * QK_STR + ty * 4];
            float4 a1 = *(float4*)&Qs[d * QK_STR + 64 + ty * 4];
            float4 b0 = *(float4*)&Ks[d * QK_STR + tx * 4];
            float4 b1 = *(float4*)&Ks[d * QK_STR + 64 + tx * 4];
            float a[8] = {a0.x, a0.y, a0.z, a0.w, a1.x, a1.y, a1.z, a1.w};
            float b[8] = {b0.x, b0.y, b0.z, b0.w, b1.x, b1.y, b1.z, b1.w};
#pragma unroll
            for (int i = 0; i < 8; i++)
#pragma unroll
                for (int j = 0; j < 8; j++) s[i][j] += a[i] * b[j];
        }

        const float scale = 0.125f;
        const bool diag = (kt == qt);
#pragma unroll
        for (int i = 0; i < 8; i++) {
            const int rg = row_r[i];
            float4 v0, v1;
            float w0[4], w1[4];
#pragma unroll
            for (int j = 0; j < 4; j++) {
                float vA = s[i][j] * scale;
                float vB = s[i][j + 4] * scale;
                if (diag && (colA + j) > rg) vA = -1e30f;
                if (diag && (colB + j) > rg) vB = -1e30f;
                w0[j] = vA; w1[j] = vB;
            }
            v0.x = w0[0]; v0.y = w0[1]; v0.z = w0[2]; v0.w = w0[3];
            v1.x = w1[0]; v1.y = w1[1]; v1.z = w1[2]; v1.w = w1[3];
            *(float4*)&Ss[rg * QK_STR + colA] = v0;
            *(float4*)&Ss[rg * QK_STR + colB] = v1;
        }
        __syncthreads();

        {
            const int row  = t >> 1;
            const int half = t & 1;
            float* Sr = Ss + row * QK_STR + half * 64;
            float mx = -1e30f;
#pragma unroll
            for (int u = 0; u < 16; u++) {
                float4 v = *(float4*)&Sr[u * 4];
                mx = fmaxf(mx, fmaxf(fmaxf(v.x, v.y), fmaxf(v.z, v.w)));
            }
            mx = fmaxf(mx, __shfl_xor_sync(0xffffffffu, mx, 1));
            float m_old = m_s[row];
            float m_new = fmaxf(m_old, mx);
            float sum = 0.0f;
#pragma unroll
            for (int u = 0; u < 16; u++) {
                float4 v = *(float4*)&Sr[u * 4];
                v.x = fast_exp(v.x - m_new);
                v.y = fast_exp(v.y - m_new);
                v.z = fast_exp(v.z - m_new);
                v.w = fast_exp(v.w - m_new);
                *(float4*)&Sr[u * 4] = v;
                sum += (v.x + v.y) + (v.z + v.w);
            }
            sum += __shfl_xor_sync(0xffffffffu, sum, 1);
            if (half == 0) {
                float alpha = fast_exp(m_old - m_new);
                l_s[row]  = l_s[row] * alpha + sum;
                m_s[row]  = m_new;
                al_s[row] = alpha;
            }
        }
        __syncthreads();

        float al[8];
#pragma unroll
        for (int i = 0; i < 8; i++) al[i] = al_s[row_r[i]];
#pragma unroll
        for (int i = 0; i < 8; i++)
#pragma unroll
            for (int j = 0; j < 4; j++) o[i][j] *= al[i];

#pragma unroll 2
        for (int k = 0; k < 128; k += 4) {
            float4 p[8];
#pragma unroll
            for (int i = 0; i < 8; i++) p[i] = *(float4*)&Ss[row_r[i] * QK_STR + k];
            float4 vv[4];
#pragma unroll
            for (int u = 0; u < 4; u++) vv[u] = *(float4*)&Vs[(k + u) * 64 + tx * 4];
#pragma unroll
            for (int i = 0; i < 8; i++) {
                float pk[4] = {p[i].x, p[i].y, p[i].z, p[i].w};
#pragma unroll
                for (int u = 0; u < 4; u++) {
                    o[i][0] = fmaf(pk[u], vv[u].x, o[i][0]);
                    o[i][1] = fmaf(pk[u], vv[u].y, o[i][1]);
                    o[i][2] = fmaf(pk[u], vv[u].z, o[i][2]);
                    o[i][3] = fmaf(pk[u], vv[u].w, o[i][3]);
                }
            }
        }
    }

    // Epilogue: normalize, split to bf16 hi/lo, write head-major.
#pragma unroll
    for (int i = 0; i < 8; i++) {
        float inv = 1.0f / l_s[row_r[i]];
        float v0 = o[i][0] * inv, v1 = o[i][1] * inv, v2 = o[i][2] * inv, v3 = o[i][3] * inv;
        __nv_bfloat162 h01 = __floats2bfloat162_rn(v0, v1);
        __nv_bfloat162 h23 = __floats2bfloat162_rn(v2, v3);
        __nv_bfloat162 l01 = __floats2bfloat162_rn(v0 - __low2float(h01), v1 - __high2float(h01));
        __nv_bfloat162 l23 = __floats2bfloat162_rn(v2 - __low2float(h23), v3 - __high2float(h23));
        size_t base = (size_t)h * (N_TOK * HD) + (size_t)(q0 + row_r[i]) * HD + tx * 4;
        ((__nv_bfloat162*)(g_C_hi + base))[0] = h01;
        ((__nv_bfloat162*)(g_C_hi + base))[1] = h23;
        ((__nv_bfloat162*)(g_C_lo + base))[0] = l01;
        ((__nv_bfloat162*)(g_C_lo + base))[1] = l23;
    }
}

extern "C" void kernel_launch(void* const* d_in, const int* in_sizes, int n_in,
                              void* d_out, int out_size) {
    const float* x  = (const float*)d_in[0];
    const float* Wq = (const float*)d_in[1];
    const float* Wk = (const float*)d_in[2];
    const float* Wv = (const float*)d_in[3];
    const float* Wo = (const float*)d_in[4];
    const float* bo = (const float*)d_in[5];
    float* out = (float*)d_out;

    cudaFuncSetAttribute(attn_kernel, cudaFuncAttributeMaxDynamicSharedMemorySize, ATTN_SMEM);

    split_x<<<(N_TOK * D_MODEL / 4) / 256, 256>>>(x);
    wprep<<<dim3(32, 32, 4), dim3(32, 8)>>>(Wq, Wk, Wv, Wo);
    mma_gemm<<<dim3(8, 32, 3), 256>>>(0, nullptr, nullptr);
    attn_kernel<<<dim3(N_TOK / 128, NH), 256, ATTN_SMEM>>>();
    mma_gemm<<<dim3(8, 32, 1), 256>>>(1, out, bo);
}